// round 10
// baseline (speedup 1.0000x reference)
#include <cuda_runtime.h>
#include <cuda_fp16.h>

#define N 4096
#define D 512
#define NCLASS 100
#define INTRA_BLOCKS 256
#define INTRA_THREADS 256

__device__ __half g_zh[N * D];     // normalized z, fp16
__device__ float g_eadv[N];        // exp(cos(z, z_adv)/T)
__device__ int   g_count[NCLASS];
__device__ int   g_offset[NCLASS];
__device__ int   g_members[N];     // row indices grouped by class (stable order)
__device__ int   g_sclass[N];      // class id per slot
__device__ float g_partial[INTRA_BLOCKS];
__device__ unsigned int g_done;

__constant__ float c_invT = 2.0f;  // 1 / TEMPERATURE
__constant__ float c_eps  = 1e-8f;

// load 16 halfs (one row's lane-share) as 8 float2
__device__ __forceinline__ void load16(const __half* rowp, int lane, float2* f) {
    const uint4* p = reinterpret_cast<const uint4*>(rowp);
    uint4 u0 = p[lane];
    uint4 u1 = p[lane + 32];
    const __half2* h0 = reinterpret_cast<const __half2*>(&u0);
    const __half2* h1 = reinterpret_cast<const __half2*>(&u1);
#pragma unroll
    for (int k = 0; k < 4; k++) f[k] = __half22float2(h0[k]);
#pragma unroll
    for (int k = 0; k < 4; k++) f[4 + k] = __half22float2(h1[k]);
}

__device__ __forceinline__ float dot8(const float2* a, const float2* b) {
    float s = 0.0f;
#pragma unroll
    for (int k = 0; k < 8; k++) s += a[k].x * b[k].x + a[k].y * b[k].y;
    return s;
}

// ---------------------------------------------------------------------------
// Fused: block 0 does the label decode + STABLE match_any counting sort
// (placed FIRST so it overlaps the norm wave). Blocks 1..N normalize row b-1
// into fp16 g_zh and compute e_adv.
// ---------------------------------------------------------------------------
__global__ void k_norm_labels(const float* __restrict__ z,
                              const float* __restrict__ za,
                              const int* __restrict__ lab) {
    if (blockIdx.x != 0) {
        // ---- normalize path ----
        int row = blockIdx.x - 1;
        int t = threadIdx.x;  // 0..127
        const float4* zr  = reinterpret_cast<const float4*>(z  + (size_t)row * D);
        const float4* zar = reinterpret_cast<const float4*>(za + (size_t)row * D);
        float4 v = zr[t];
        float4 w = zar[t];
        float sz = v.x * v.x + v.y * v.y + v.z * v.z + v.w * v.w;
        float sa = w.x * w.x + w.y * w.y + w.z * w.z + w.w * w.w;
        float dd = v.x * w.x + v.y * w.y + v.z * w.z + v.w * w.w;
#pragma unroll
        for (int o = 16; o; o >>= 1) {
            sz += __shfl_xor_sync(0xffffffffu, sz, o);
            sa += __shfl_xor_sync(0xffffffffu, sa, o);
            dd += __shfl_xor_sync(0xffffffffu, dd, o);
        }
        __shared__ float s1[4], s2[4], s3[4];
        int wid = t >> 5, lid = t & 31;
        if (lid == 0) { s1[wid] = sz; s2[wid] = sa; s3[wid] = dd; }
        __syncthreads();
        sz = s1[0] + s1[1] + s1[2] + s1[3];
        sa = s2[0] + s2[1] + s2[2] + s2[3];
        dd = s3[0] + s3[1] + s3[2] + s3[3];

        float invz  = 1.0f / fmaxf(sqrtf(sz), c_eps);
        float invza = 1.0f / fmaxf(sqrtf(sa), c_eps);

        __half2 h0 = __floats2half2_rn(v.x * invz, v.y * invz);
        __half2 h1 = __floats2half2_rn(v.z * invz, v.w * invz);
        uint2 packed = make_uint2(*reinterpret_cast<unsigned*>(&h0),
                                  *reinterpret_cast<unsigned*>(&h1));
        reinterpret_cast<uint2*>(g_zh + (size_t)row * D)[t] = packed;

        if (t == 0) g_eadv[row] = expf(dd * invz * invza * c_invT);
        return;
    }

    // ---- label sort path (block 0: 128 threads = 4 warps) ----
    __shared__ int sl[N];              // 16 KB decoded labels
    __shared__ int whist[4][NCLASS];
    __shared__ int cls_cnt[NCLASS];
    __shared__ int cls_off[NCLASS];
    __shared__ int ok;
    int t = threadIdx.x;
    int lane = t & 31, w = t >> 5;

    if (t == 0) { ok = 1; g_done = 0u; }
    __syncthreads();
    // int64 labels in [0,100): odd 32-bit words are 0, even in range.
    bool good = true;
    for (int k = t; k < N / 2; k += 128) {
        int lo = lab[2 * k];
        int hi = lab[2 * k + 1];
        if (hi != 0 || lo < 0 || lo >= NCLASS) good = false;
    }
    if (!good) atomicExch(&ok, 0);
    __syncthreads();
    int is64 = ok;

    for (int i = t; i < N; i += 128) sl[i] = is64 ? lab[2 * i] : lab[i];
    for (int c = lane; c < NCLASS; c += 32) whist[w][c] = 0;
    __syncthreads();

    // count pass: warp w owns rows [w*1024, w*1024+1024), 32 iters of 32
    int rbase = w * 1024;
#pragma unroll 1
    for (int it = 0; it < 32; it++) {
        int c = sl[rbase + it * 32 + lane];
        unsigned mask = __match_any_sync(0xffffffffu, c);
        int leader = __ffs(mask) - 1;
        if (lane == leader) whist[w][c] += __popc(mask);
        __syncwarp();
    }
    __syncthreads();

    // cross-warp exclusive scan per class (thread per class, 4 steps)
    if (t < NCLASS) {
        int run = 0;
#pragma unroll
        for (int k = 0; k < 4; k++) {
            int v = whist[k][t];
            whist[k][t] = run;
            run += v;
        }
        cls_cnt[t] = run;
    }
    __syncthreads();

    // class offsets: warp 0, 4 SHFL scan segments over 100 counts
    if (w == 0) {
        int carry = 0;
#pragma unroll
        for (int seg = 0; seg < 4; seg++) {
            int c = seg * 32 + lane;
            int v = (c < NCLASS) ? cls_cnt[c] : 0;
            int inc = v;
#pragma unroll
            for (int o = 1; o < 32; o <<= 1) {
                int y = __shfl_up_sync(0xffffffffu, inc, o);
                if (lane >= o) inc += y;
            }
            if (c < NCLASS) cls_off[c] = inc - v + carry;
            carry += __shfl_sync(0xffffffffu, inc, 31);
        }
    }
    __syncthreads();

    // stable emit: match_any rank within each 32-row group, leader bumps base
#pragma unroll 1
    for (int it = 0; it < 32; it++) {
        int row = rbase + it * 32 + lane;
        int c = sl[row];
        unsigned mask = __match_any_sync(0xffffffffu, c);
        int rank = __popc(mask & ((1u << lane) - 1u));
        int base = whist[w][c];          // same-class lanes broadcast-read
        int pos = cls_off[c] + base + rank;
        g_members[pos] = row;
        g_sclass[pos] = c;
        int leader = __ffs(mask) - 1;
        if (lane == leader) whist[w][c] = base + __popc(mask);
        __syncwarp();
    }
    if (t < NCLASS) { g_count[t] = cls_cnt[t]; g_offset[t] = cls_off[t]; }
}

// single-row fallback for warps whose two slots straddle a class boundary
__device__ float row_acc(int i, int off, int cnt, int lane, const float2* a) {
    float acc = 0.0f;
    for (int m = 0; m < cnt; m++) {
        int j = g_members[off + m];
        float2 p[8];
        load16(g_zh + (size_t)j * D, lane, p);
        float s = dot8(a, p);
#pragma unroll
        for (int o = 16; o; o >>= 1) s += __shfl_xor_sync(0xffffffffu, s, o);
        acc += (j != i) ? __expf(s * c_invT) : 0.0f;
    }
    return acc;
}

// ---------------------------------------------------------------------------
// Main: warp owns TWO adjacent slots (2w, 2w+1) of the class-sorted order.
// 2 i-rows x 2 j-rows register tile: each j load feeds 4 dots; 4 independent
// shfl/exp chains. fp16 rows halve traffic. Ticket last-block reduction.
// ---------------------------------------------------------------------------
__global__ void __launch_bounds__(INTRA_THREADS)
k_intra(float* __restrict__ out) {
    __shared__ float warp_loss[INTRA_THREADS / 32];
    __shared__ bool is_last;
    int w = (blockIdx.x * blockDim.x + threadIdx.x) >> 5;   // 0..2047
    int lane = threadIdx.x & 31;
    int wid = threadIdx.x >> 5;

    int s0 = 2 * w, s1 = 2 * w + 1;
    int c0 = g_sclass[s0], c1 = g_sclass[s1];
    int iA = g_members[s0], iB = g_members[s1];

    float2 a[8], b[8];
    load16(g_zh + (size_t)iA * D, lane, a);
    load16(g_zh + (size_t)iB * D, lane, b);

    float accA = 0.0f, accB = 0.0f;
    if (c0 == c1) {
        int off = g_offset[c0];
        int cnt = g_count[c0];
        int m = 0;
        for (; m + 2 <= cnt; m += 2) {
            int j0 = g_members[off + m];
            int j1 = g_members[off + m + 1];
            float2 p[8], q[8];
            load16(g_zh + (size_t)j0 * D, lane, p);
            load16(g_zh + (size_t)j1 * D, lane, q);
            float s00 = dot8(a, p), s01 = dot8(a, q);
            float s10 = dot8(b, p), s11 = dot8(b, q);
#pragma unroll
            for (int o = 16; o; o >>= 1) {
                s00 += __shfl_xor_sync(0xffffffffu, s00, o);
                s01 += __shfl_xor_sync(0xffffffffu, s01, o);
                s10 += __shfl_xor_sync(0xffffffffu, s10, o);
                s11 += __shfl_xor_sync(0xffffffffu, s11, o);
            }
            float e00 = __expf(s00 * c_invT);
            float e01 = __expf(s01 * c_invT);
            float e10 = __expf(s10 * c_invT);
            float e11 = __expf(s11 * c_invT);
            accA += (j0 != iA) ? e00 : 0.0f;
            accA += (j1 != iA) ? e01 : 0.0f;
            accB += (j0 != iB) ? e10 : 0.0f;
            accB += (j1 != iB) ? e11 : 0.0f;
        }
        if (m < cnt) {
            int j0 = g_members[off + m];
            float2 p[8];
            load16(g_zh + (size_t)j0 * D, lane, p);
            float s00 = dot8(a, p), s10 = dot8(b, p);
#pragma unroll
            for (int o = 16; o; o >>= 1) {
                s00 += __shfl_xor_sync(0xffffffffu, s00, o);
                s10 += __shfl_xor_sync(0xffffffffu, s10, o);
            }
            accA += (j0 != iA) ? __expf(s00 * c_invT) : 0.0f;
            accB += (j0 != iB) ? __expf(s10 * c_invT) : 0.0f;
        }
    } else {
        accA = row_acc(iA, g_offset[c0], g_count[c0], lane, a);
        accB = row_acc(iB, g_offset[c1], g_count[c1], lane, b);
    }

    // per-warp loss -> block partial (fixed order => deterministic)
    if (lane == 0)
        warp_loss[wid] = log1pf(accA / g_eadv[iA]) + log1pf(accB / g_eadv[iB]);
    __syncthreads();
    if (threadIdx.x == 0) {
        float bsum = 0.0f;
#pragma unroll
        for (int ww = 0; ww < INTRA_THREADS / 32; ww++) bsum += warp_loss[ww];
        g_partial[blockIdx.x] = bsum;
        __threadfence();
        unsigned int ticket = atomicAdd(&g_done, 1u);
        is_last = (ticket == INTRA_BLOCKS - 1);
    }
    __syncthreads();

    // last-arriving block: deterministic fixed-tree reduction of 256 partials
    if (is_last) {
        __shared__ float sm[INTRA_BLOCKS];
        int t = threadIdx.x;
        __threadfence();
        sm[t] = g_partial[t];
        __syncthreads();
#pragma unroll
        for (int o = INTRA_BLOCKS / 2; o > 0; o >>= 1) {
            if (t < o) sm[t] += sm[t + o];
            __syncthreads();
        }
        if (t == 0) out[0] = sm[0] * (1.0f / (float)N);
    }
}

extern "C" void kernel_launch(void* const* d_in, const int* in_sizes, int n_in,
                              void* d_out, int out_size) {
    const float* z   = (const float*)d_in[0];
    const float* za  = (const float*)d_in[1];
    const int*   lab = (const int*)d_in[2];
    float* out = (float*)d_out;

    k_norm_labels<<<N + 1, 128>>>(z, za, lab);
    k_intra<<<INTRA_BLOCKS, INTRA_THREADS>>>(out);
}

// round 11
// speedup vs baseline: 1.0964x; 1.0964x over previous
#include <cuda_runtime.h>
#include <cuda_fp16.h>

#define N 4096
#define D 512
#define D2 256            // D/2 half2 per row
#define NCLASS 100
#define INTRA_BLOCKS 512
#define INTRA_THREADS 256

__device__ __half g_zh[N * D];         // normalized z, fp16, row-major
__device__ __half2 g_zt[D2][N];        // transposed + class-slot-permuted (4 MB)
__device__ float g_eadv[N];            // exp(cos(z, z_adv)/T)
__device__ int   g_count[NCLASS];
__device__ int   g_offset[NCLASS];
__device__ int   g_members[N];         // row indices grouped by class (stable)
__device__ int   g_sclass[N];          // class id per slot
__device__ float g_partial[INTRA_BLOCKS];
__device__ unsigned int g_done;

__constant__ float c_invT = 2.0f;      // 1 / TEMPERATURE
__constant__ float c_eps  = 1e-8f;

// ---------------------------------------------------------------------------
// Kernel 1 (513 blocks x 256 thr). Block 0: label decode + STABLE match_any
// counting sort (8 warps). Blocks 1..512: warp-per-row normalize -> g_zh fp16
// + e_adv. Sort overlaps the norm wave.
// ---------------------------------------------------------------------------
__global__ void __launch_bounds__(256)
k_norm_labels(const float* __restrict__ z,
              const float* __restrict__ za,
              const int* __restrict__ lab) {
    int t = threadIdx.x;
    int lane = t & 31, w = t >> 5;

    if (blockIdx.x != 0) {
        // ---- normalize path: warp per row ----
        int row = (blockIdx.x - 1) * 8 + w;
        const float4* zr  = reinterpret_cast<const float4*>(z  + (size_t)row * D);
        const float4* zar = reinterpret_cast<const float4*>(za + (size_t)row * D);
        float4 v[4], u[4];
#pragma unroll
        for (int k = 0; k < 4; k++) { v[k] = zr[lane + 32 * k]; u[k] = zar[lane + 32 * k]; }
        float sz = 0.0f, sa = 0.0f, dd = 0.0f;
#pragma unroll
        for (int k = 0; k < 4; k++) {
            sz += v[k].x * v[k].x + v[k].y * v[k].y + v[k].z * v[k].z + v[k].w * v[k].w;
            sa += u[k].x * u[k].x + u[k].y * u[k].y + u[k].z * u[k].z + u[k].w * u[k].w;
            dd += v[k].x * u[k].x + v[k].y * u[k].y + v[k].z * u[k].z + v[k].w * u[k].w;
        }
#pragma unroll
        for (int o = 16; o; o >>= 1) {
            sz += __shfl_xor_sync(0xffffffffu, sz, o);
            sa += __shfl_xor_sync(0xffffffffu, sa, o);
            dd += __shfl_xor_sync(0xffffffffu, dd, o);
        }
        float invz  = 1.0f / fmaxf(sqrtf(sz), c_eps);
        float invza = 1.0f / fmaxf(sqrtf(sa), c_eps);
#pragma unroll
        for (int k = 0; k < 4; k++) {
            __half2 h0 = __floats2half2_rn(v[k].x * invz, v[k].y * invz);
            __half2 h1 = __floats2half2_rn(v[k].z * invz, v[k].w * invz);
            uint2 packed = make_uint2(*reinterpret_cast<unsigned*>(&h0),
                                      *reinterpret_cast<unsigned*>(&h1));
            reinterpret_cast<uint2*>(g_zh + (size_t)row * D)[lane + 32 * k] = packed;
        }
        if (lane == 0) g_eadv[row] = expf(dd * invz * invza * c_invT);
        return;
    }

    // ---- label sort path (block 0: 8 warps) ----
    __shared__ int sl[N];              // 16 KB decoded labels
    __shared__ int whist[8][NCLASS];
    __shared__ int cls_cnt[NCLASS];
    __shared__ int cls_off[NCLASS];
    __shared__ int ok;

    if (t == 0) { ok = 1; g_done = 0u; }
    __syncthreads();
    // int64 labels in [0,100): odd 32-bit words are 0, even in range.
    bool good = true;
    for (int k = t; k < N / 2; k += 256) {
        int lo = lab[2 * k];
        int hi = lab[2 * k + 1];
        if (hi != 0 || lo < 0 || lo >= NCLASS) good = false;
    }
    if (!good) atomicExch(&ok, 0);
    __syncthreads();
    int is64 = ok;

    for (int i = t; i < N; i += 256) sl[i] = is64 ? lab[2 * i] : lab[i];
    for (int c = lane; c < NCLASS; c += 32) whist[w][c] = 0;
    __syncthreads();

    // count pass: warp w owns rows [w*512, w*512+512), 16 iters of 32
    int rbase = w * 512;
#pragma unroll 1
    for (int it = 0; it < 16; it++) {
        int c = sl[rbase + it * 32 + lane];
        unsigned mask = __match_any_sync(0xffffffffu, c);
        int leader = __ffs(mask) - 1;
        if (lane == leader) whist[w][c] += __popc(mask);
        __syncwarp();
    }
    __syncthreads();

    // cross-warp exclusive scan per class (thread per class, 8 steps)
    if (t < NCLASS) {
        int run = 0;
#pragma unroll
        for (int k = 0; k < 8; k++) {
            int v = whist[k][t];
            whist[k][t] = run;
            run += v;
        }
        cls_cnt[t] = run;
    }
    __syncthreads();

    // class offsets: warp 0, 4 SHFL scan segments over 100 counts
    if (w == 0) {
        int carry = 0;
#pragma unroll
        for (int seg = 0; seg < 4; seg++) {
            int c = seg * 32 + lane;
            int v = (c < NCLASS) ? cls_cnt[c] : 0;
            int inc = v;
#pragma unroll
            for (int o = 1; o < 32; o <<= 1) {
                int y = __shfl_up_sync(0xffffffffu, inc, o);
                if (lane >= o) inc += y;
            }
            if (c < NCLASS) cls_off[c] = inc - v + carry;
            carry += __shfl_sync(0xffffffffu, inc, 31);
        }
    }
    __syncthreads();

    // stable emit
#pragma unroll 1
    for (int it = 0; it < 16; it++) {
        int row = rbase + it * 32 + lane;
        int c = sl[row];
        unsigned mask = __match_any_sync(0xffffffffu, c);
        int rank = __popc(mask & ((1u << lane) - 1u));
        int base = whist[w][c];
        int pos = cls_off[c] + base + rank;
        g_members[pos] = row;
        g_sclass[pos] = c;
        int leader = __ffs(mask) - 1;
        if (lane == leader) whist[w][c] = base + __popc(mask);
        __syncwarp();
    }
    if (t < NCLASS) { g_count[t] = cls_cnt[t]; g_offset[t] = cls_off[t]; }
}

// ---------------------------------------------------------------------------
// Kernel 2: permuted transpose. g_zt[d2][slot] = row g_members[slot], dims
// (2*d2, 2*d2+1) as half2. 128 blocks x 256 thr: 16 slot-tiles x 8 d2-tiles.
// Reads 128B contiguous per thread; writes coalesced.
// ---------------------------------------------------------------------------
__global__ void __launch_bounds__(256)
k_perm() {
    int st = blockIdx.x & 15;          // slot tile
    int dt = blockIdx.x >> 4;          // d2 tile
    int s = st * 256 + threadIdx.x;
    int i = g_members[s];
    const __half2* src = reinterpret_cast<const __half2*>(g_zh + (size_t)i * D) + dt * 32;
#pragma unroll
    for (int k = 0; k < 32; k++)
        g_zt[dt * 32 + k][s] = src[k];
}

// ---------------------------------------------------------------------------
// Kernel 3: warp per slot s (i-row). Lane l owns pair (i, slot off+32g+l):
// full 512-dim dot accumulated serially from coalesced g_zt columns — NO
// per-pair shuffle. HFMA2 with fp32 flush every 16 d2. One butterfly per
// warp at the end. Ticket last-block final reduction.
// ---------------------------------------------------------------------------
__global__ void __launch_bounds__(INTRA_THREADS)
k_intra(float* __restrict__ out) {
    __shared__ __half2 sa[8][D2];      // staged i-rows, 4 KB
    __shared__ float warp_loss[INTRA_THREADS / 32];
    __shared__ bool is_last;
    int wid = threadIdx.x >> 5;
    int lane = threadIdx.x & 31;
    int s = blockIdx.x * 8 + wid;      // slot 0..4095

    int i = g_members[s];
    int c = g_sclass[s];
    int off = g_offset[c];
    int cnt = g_count[c];

    // stage row i (1 KB) into smem
    {
        const uint4* rp = reinterpret_cast<const uint4*>(g_zh + (size_t)i * D);
        uint4* dp = reinterpret_cast<uint4*>(sa[wid]);
        dp[lane] = rp[lane];
        dp[lane + 32] = rp[lane + 32];
    }
    __syncwarp();

    float acc = 0.0f;
    for (int g = 0; g * 32 < cnt; g++) {
        int m = g * 32 + lane;
        bool valid = (m < cnt);
        int js = valid ? (off + m) : off;      // clamped safe slot
        float dot = 0.0f;
        __half2 h0 = __float2half2_rn(0.0f);
        __half2 h1 = __float2half2_rn(0.0f);
#pragma unroll 1
        for (int chunk = 0; chunk < 16; chunk++) {
            int d2 = chunk * 16;
#pragma unroll
            for (int k = 0; k < 16; k += 2) {
                h0 = __hfma2(sa[wid][d2 + k],     g_zt[d2 + k][js],     h0);
                h1 = __hfma2(sa[wid][d2 + k + 1], g_zt[d2 + k + 1][js], h1);
            }
            __half2 hs = __hadd2(h0, h1);
            float2 f = __half22float2(hs);
            dot += f.x + f.y;
            h0 = __float2half2_rn(0.0f);
            h1 = __float2half2_rn(0.0f);
        }
        bool count_it = valid && (off + m != s);   // mask diagonal + tail
        acc += count_it ? __expf(dot * c_invT) : 0.0f;
    }
    // one butterfly per warp
#pragma unroll
    for (int o = 16; o; o >>= 1) acc += __shfl_xor_sync(0xffffffffu, acc, o);

    if (lane == 0) warp_loss[wid] = log1pf(acc / g_eadv[i]);
    __syncthreads();
    if (threadIdx.x == 0) {
        float bsum = 0.0f;
#pragma unroll
        for (int ww = 0; ww < INTRA_THREADS / 32; ww++) bsum += warp_loss[ww];
        g_partial[blockIdx.x] = bsum;
        __threadfence();
        unsigned int ticket = atomicAdd(&g_done, 1u);
        is_last = (ticket == INTRA_BLOCKS - 1);
    }
    __syncthreads();

    if (is_last) {
        __shared__ float sm[INTRA_THREADS];
        int t = threadIdx.x;
        __threadfence();
        sm[t] = g_partial[t] + g_partial[t + INTRA_THREADS];
        __syncthreads();
#pragma unroll
        for (int o = INTRA_THREADS / 2; o > 0; o >>= 1) {
            if (t < o) sm[t] += sm[t + o];
            __syncthreads();
        }
        if (t == 0) out[0] = sm[0] * (1.0f / (float)N);
    }
}

extern "C" void kernel_launch(void* const* d_in, const int* in_sizes, int n_in,
                              void* d_out, int out_size) {
    const float* z   = (const float*)d_in[0];
    const float* za  = (const float*)d_in[1];
    const int*   lab = (const int*)d_in[2];
    float* out = (float*)d_out;

    k_norm_labels<<<513, 256>>>(z, za, lab);
    k_perm<<<128, 256>>>();
    k_intra<<<INTRA_BLOCKS, INTRA_THREADS>>>(out);
}

// round 12
// speedup vs baseline: 1.5363x; 1.4012x over previous
#include <cuda_runtime.h>
#include <cuda_fp16.h>

#define N 4096
#define D 512
#define NCLASS 100
#define GRID 512
#define THREADS 256

__device__ __half g_zh[N * D];     // normalized z, fp16
__device__ float g_eadv[N];        // exp(cos(z, z_adv)/T)
__device__ int   g_count[NCLASS];
__device__ int   g_offset[NCLASS];
__device__ int   g_members[N];     // row indices grouped by class (stable)
__device__ int   g_sclass[N];      // class id per slot
__device__ float g_partial[GRID];
__device__ unsigned int g_done;
__device__ unsigned int g_bar_count;           // returns to 0 after each barrier
__device__ volatile unsigned int g_bar_gen;    // monotonically increasing

__constant__ float c_invT = 2.0f;  // 1 / TEMPERATURE
__constant__ float c_eps  = 1e-8f;

// generation grid barrier: all GRID blocks are co-resident (enforced by
// __launch_bounds__), so the spin cannot deadlock. Deterministic: affects
// only ordering, not arithmetic.
__device__ __forceinline__ void grid_sync() {
    __syncthreads();
    if (threadIdx.x == 0) {
        unsigned int mygen = g_bar_gen;
        __threadfence();
        unsigned int old = atomicAdd(&g_bar_count, 1u);
        if (old == GRID - 1) {
            g_bar_count = 0;
            __threadfence();
            g_bar_gen = mygen + 1;
        } else {
            while (g_bar_gen == mygen) __nanosleep(64);
        }
        __threadfence();
    }
    __syncthreads();
}

// load one row's lane-share (16 halfs) as 8 float2
__device__ __forceinline__ void loadrow(const __half* rowp, int lane, float2* f) {
    const uint4* p = reinterpret_cast<const uint4*>(rowp);
    uint4 u0 = p[lane];
    uint4 u1 = p[lane + 32];
    const __half2* h0 = reinterpret_cast<const __half2*>(&u0);
    const __half2* h1 = reinterpret_cast<const __half2*>(&u1);
#pragma unroll
    for (int k = 0; k < 4; k++) f[k] = __half22float2(h0[k]);
#pragma unroll
    for (int k = 0; k < 4; k++) f[4 + k] = __half22float2(h1[k]);
}

__device__ __forceinline__ float dot8(const float2* a, const float2* b) {
    float s = 0.0f;
#pragma unroll
    for (int k = 0; k < 8; k++) s += a[k].x * b[k].x + a[k].y * b[k].y;
    return s;
}

__global__ void __launch_bounds__(THREADS, 4)
k_all(const float* __restrict__ z, const float* __restrict__ za,
      const int* __restrict__ lab, float* __restrict__ out) {
    // -------- shared memory (sort arrays used by block 0 only) --------
    __shared__ int sl[N];              // 16 KB decoded labels
    __shared__ int whist[8][NCLASS];   // 3.2 KB
    __shared__ int cls_cnt[NCLASS];
    __shared__ int cls_off[NCLASS];
    __shared__ int ok;
    __shared__ float warp_loss[8];
    __shared__ bool is_last;
    __shared__ float smr[THREADS];

    int t = threadIdx.x;
    int lane = t & 31, w = t >> 5;

    // ================= Phase A: normalize (all blocks) =================
    {
        int row = blockIdx.x * 8 + w;   // 512*8 = 4096 rows exactly
        const float4* zr  = reinterpret_cast<const float4*>(z  + (size_t)row * D);
        const float4* zar = reinterpret_cast<const float4*>(za + (size_t)row * D);
        float4 v[4], u[4];
#pragma unroll
        for (int k = 0; k < 4; k++) { v[k] = zr[lane + 32 * k]; u[k] = zar[lane + 32 * k]; }
        float sz = 0.0f, sa = 0.0f, dd = 0.0f;
#pragma unroll
        for (int k = 0; k < 4; k++) {
            sz += v[k].x * v[k].x + v[k].y * v[k].y + v[k].z * v[k].z + v[k].w * v[k].w;
            sa += u[k].x * u[k].x + u[k].y * u[k].y + u[k].z * u[k].z + u[k].w * u[k].w;
            dd += v[k].x * u[k].x + v[k].y * u[k].y + v[k].z * u[k].z + v[k].w * u[k].w;
        }
#pragma unroll
        for (int o = 16; o; o >>= 1) {
            sz += __shfl_xor_sync(0xffffffffu, sz, o);
            sa += __shfl_xor_sync(0xffffffffu, sa, o);
            dd += __shfl_xor_sync(0xffffffffu, dd, o);
        }
        float invz  = 1.0f / fmaxf(sqrtf(sz), c_eps);
        float invza = 1.0f / fmaxf(sqrtf(sa), c_eps);
#pragma unroll
        for (int k = 0; k < 4; k++) {
            __half2 h0 = __floats2half2_rn(v[k].x * invz, v[k].y * invz);
            __half2 h1 = __floats2half2_rn(v[k].z * invz, v[k].w * invz);
            uint2 packed = make_uint2(*reinterpret_cast<unsigned*>(&h0),
                                      *reinterpret_cast<unsigned*>(&h1));
            reinterpret_cast<uint2*>(g_zh + (size_t)row * D)[lane + 32 * k] = packed;
        }
        if (lane == 0) g_eadv[row] = expf(dd * invz * invza * c_invT);
    }

    // ================= Phase A': label sort (block 0 only) =================
    if (blockIdx.x == 0) {
        if (t == 0) { ok = 1; g_done = 0u; }
        __syncthreads();
        // int64 labels in [0,100): odd 32-bit words are 0, even in range.
        bool good = true;
        for (int k = t; k < N / 2; k += THREADS) {
            int lo = lab[2 * k];
            int hi = lab[2 * k + 1];
            if (hi != 0 || lo < 0 || lo >= NCLASS) good = false;
        }
        if (!good) atomicExch(&ok, 0);
        __syncthreads();
        int is64 = ok;

        for (int i = t; i < N; i += THREADS) sl[i] = is64 ? lab[2 * i] : lab[i];
        for (int c = lane; c < NCLASS; c += 32) whist[w][c] = 0;
        __syncthreads();

        // count pass: warp w owns rows [w*512, w*512+512), 16 iters of 32
        int rbase = w * 512;
#pragma unroll 1
        for (int it = 0; it < 16; it++) {
            int c = sl[rbase + it * 32 + lane];
            unsigned mask = __match_any_sync(0xffffffffu, c);
            int leader = __ffs(mask) - 1;
            if (lane == leader) whist[w][c] += __popc(mask);
            __syncwarp();
        }
        __syncthreads();

        // cross-warp exclusive scan per class (thread per class, 8 steps)
        if (t < NCLASS) {
            int run = 0;
#pragma unroll
            for (int k = 0; k < 8; k++) {
                int v = whist[k][t];
                whist[k][t] = run;
                run += v;
            }
            cls_cnt[t] = run;
        }
        __syncthreads();

        // class offsets: warp 0, 4 SHFL scan segments over 100 counts
        if (w == 0) {
            int carry = 0;
#pragma unroll
            for (int seg = 0; seg < 4; seg++) {
                int c = seg * 32 + lane;
                int v = (c < NCLASS) ? cls_cnt[c] : 0;
                int inc = v;
#pragma unroll
                for (int o = 1; o < 32; o <<= 1) {
                    int y = __shfl_up_sync(0xffffffffu, inc, o);
                    if (lane >= o) inc += y;
                }
                if (c < NCLASS) cls_off[c] = inc - v + carry;
                carry += __shfl_sync(0xffffffffu, inc, 31);
            }
        }
        __syncthreads();

        // stable emit
#pragma unroll 1
        for (int it = 0; it < 16; it++) {
            int row = rbase + it * 32 + lane;
            int c = sl[row];
            unsigned mask = __match_any_sync(0xffffffffu, c);
            int rank = __popc(mask & ((1u << lane) - 1u));
            int base = whist[w][c];
            int pos = cls_off[c] + base + rank;
            g_members[pos] = row;
            g_sclass[pos] = c;
            int leader = __ffs(mask) - 1;
            if (lane == leader) whist[w][c] = base + __popc(mask);
            __syncwarp();
        }
        if (t < NCLASS) { g_count[t] = cls_cnt[t]; g_offset[t] = cls_off[t]; }
    }

    // ================= grid barrier =================
    grid_sync();

    // ================= Phase B: intra (warp per slot) =================
    {
        int s = blockIdx.x * 8 + w;        // slot 0..4095
        int i = g_members[s];
        int c = g_sclass[s];
        int off = g_offset[c];
        int cnt = g_count[c];

        float2 a[8];
        loadrow(g_zh + (size_t)i * D, lane, a);

        float acc = 0.0f;
        int m = 0;
        for (; m + 4 <= cnt; m += 4) {
            int j0 = g_members[off + m];
            int j1 = g_members[off + m + 1];
            int j2 = g_members[off + m + 2];
            int j3 = g_members[off + m + 3];
            const uint4* A0 = reinterpret_cast<const uint4*>(g_zh + (size_t)j0 * D);
            const uint4* A1 = reinterpret_cast<const uint4*>(g_zh + (size_t)j1 * D);
            const uint4* A2 = reinterpret_cast<const uint4*>(g_zh + (size_t)j2 * D);
            const uint4* A3 = reinterpret_cast<const uint4*>(g_zh + (size_t)j3 * D);
            float s0 = 0.0f, s1 = 0.0f, s2 = 0.0f, s3 = 0.0f;
#pragma unroll
            for (int half = 0; half < 2; half++) {
                int idx = lane + half * 32;
                uint4 u0 = A0[idx], u1 = A1[idx], u2 = A2[idx], u3 = A3[idx];
                const __half2* H0 = reinterpret_cast<const __half2*>(&u0);
                const __half2* H1 = reinterpret_cast<const __half2*>(&u1);
                const __half2* H2 = reinterpret_cast<const __half2*>(&u2);
                const __half2* H3 = reinterpret_cast<const __half2*>(&u3);
#pragma unroll
                for (int k = 0; k < 4; k++) {
                    float2 av = a[half * 4 + k];
                    float2 f0 = __half22float2(H0[k]);
                    float2 f1 = __half22float2(H1[k]);
                    float2 f2 = __half22float2(H2[k]);
                    float2 f3 = __half22float2(H3[k]);
                    s0 += av.x * f0.x + av.y * f0.y;
                    s1 += av.x * f1.x + av.y * f1.y;
                    s2 += av.x * f2.x + av.y * f2.y;
                    s3 += av.x * f3.x + av.y * f3.y;
                }
            }
#pragma unroll
            for (int o = 16; o; o >>= 1) {
                s0 += __shfl_xor_sync(0xffffffffu, s0, o);
                s1 += __shfl_xor_sync(0xffffffffu, s1, o);
                s2 += __shfl_xor_sync(0xffffffffu, s2, o);
                s3 += __shfl_xor_sync(0xffffffffu, s3, o);
            }
            float e0 = __expf(s0 * c_invT);
            float e1 = __expf(s1 * c_invT);
            float e2 = __expf(s2 * c_invT);
            float e3 = __expf(s3 * c_invT);
            acc += (j0 != i) ? e0 : 0.0f;
            acc += (j1 != i) ? e1 : 0.0f;
            acc += (j2 != i) ? e2 : 0.0f;
            acc += (j3 != i) ? e3 : 0.0f;
        }
        for (; m < cnt; m++) {
            int j0 = g_members[off + m];
            float2 p[8];
            loadrow(g_zh + (size_t)j0 * D, lane, p);
            float s0 = dot8(a, p);
#pragma unroll
            for (int o = 16; o; o >>= 1) s0 += __shfl_xor_sync(0xffffffffu, s0, o);
            acc += (j0 != i) ? __expf(s0 * c_invT) : 0.0f;
        }

        if (lane == 0) warp_loss[w] = log1pf(acc / g_eadv[i]);
    }
    __syncthreads();

    // ================= Phase C: ticketed final reduction =================
    if (t == 0) {
        float bsum = 0.0f;
#pragma unroll
        for (int ww = 0; ww < 8; ww++) bsum += warp_loss[ww];
        g_partial[blockIdx.x] = bsum;
        __threadfence();
        unsigned int ticket = atomicAdd(&g_done, 1u);
        is_last = (ticket == GRID - 1);
    }
    __syncthreads();

    if (is_last) {
        __threadfence();
        smr[t] = g_partial[t] + g_partial[t + THREADS];
        __syncthreads();
#pragma unroll
        for (int o = THREADS / 2; o > 0; o >>= 1) {
            if (t < o) smr[t] += smr[t + o];
            __syncthreads();
        }
        if (t == 0) out[0] = smr[0] * (1.0f / (float)N);
    }
}

extern "C" void kernel_launch(void* const* d_in, const int* in_sizes, int n_in,
                              void* d_out, int out_size) {
    const float* z   = (const float*)d_in[0];
    const float* za  = (const float*)d_in[1];
    const int*   lab = (const int*)d_in[2];
    float* out = (float*)d_out;

    k_all<<<GRID, THREADS>>>(z, za, lab, out);
}

// round 13
// speedup vs baseline: 1.7061x; 1.1105x over previous
#include <cuda_runtime.h>
#include <cuda_fp16.h>

#define N 4096
#define D 512
#define NCLASS 100
#define GRID 512
#define THREADS 256

__device__ __half g_zh[N * D];     // normalized z, fp16
__device__ float g_eadv[N];        // exp(cos(z, z_adv)/T)
__device__ int   g_count[NCLASS];
__device__ int   g_offset[NCLASS];
__device__ int   g_members[N];     // row indices grouped by class (stable)
__device__ int   g_sclass[N];      // class id per slot
__device__ int   g_sl[N];          // decoded labels (sort scratch, global)
__device__ float g_partial[GRID];
__device__ unsigned int g_done;
__device__ unsigned int g_bar_count;           // returns to 0 after each barrier
__device__ volatile unsigned int g_bar_gen;    // monotonically increasing

__constant__ float c_invT = 2.0f;  // 1 / TEMPERATURE
__constant__ float c_eps  = 1e-8f;

// generation grid barrier: all GRID blocks co-resident (enforced by
// __launch_bounds__), so the spin cannot deadlock. Ordering-only.
__device__ __forceinline__ void grid_sync() {
    __syncthreads();
    if (threadIdx.x == 0) {
        unsigned int mygen = g_bar_gen;
        __threadfence();
        unsigned int old = atomicAdd(&g_bar_count, 1u);
        if (old == GRID - 1) {
            g_bar_count = 0;
            __threadfence();
            g_bar_gen = mygen + 1;
        } else {
            while (g_bar_gen == mygen) __nanosleep(64);
        }
        __threadfence();
    }
    __syncthreads();
}

// half2 dot of a lane-share (8 half2) against one packed j-row lane-share.
// Two depth-4 HFMA2 chains, fp32 flush at the end (validated: rel_err 0.0).
__device__ __forceinline__ float dot_h2(const __half2* a, uint4 u0, uint4 u1) {
    const __half2* H0 = reinterpret_cast<const __half2*>(&u0);
    const __half2* H1 = reinterpret_cast<const __half2*>(&u1);
    __half2 acc0 = __hmul2(a[0], H0[0]);
    __half2 acc1 = __hmul2(a[4], H1[0]);
#pragma unroll
    for (int k = 1; k < 4; k++) {
        acc0 = __hfma2(a[k],     H0[k], acc0);
        acc1 = __hfma2(a[4 + k], H1[k], acc1);
    }
    float2 f0 = __half22float2(acc0);
    float2 f1 = __half22float2(acc1);
    return (f0.x + f0.y) + (f1.x + f1.y);
}

__global__ void __launch_bounds__(THREADS, 4)
k_all(const float* __restrict__ z, const float* __restrict__ za,
      const int* __restrict__ lab, float* __restrict__ out) {
    __shared__ int whist[8][NCLASS];   // 3.2 KB (sort, block 0 only)
    __shared__ int cls_cnt[NCLASS];
    __shared__ int cls_off[NCLASS];
    __shared__ int ok;
    __shared__ float warp_loss[8];
    __shared__ bool is_last;
    __shared__ float smr[THREADS];

    int t = threadIdx.x;
    int lane = t & 31, w = t >> 5;

    // ================= Phase A: normalize (all blocks) =================
    {
        int row = blockIdx.x * 8 + w;   // 512*8 = 4096 rows exactly
        const float4* zr  = reinterpret_cast<const float4*>(z  + (size_t)row * D);
        const float4* zar = reinterpret_cast<const float4*>(za + (size_t)row * D);
        float4 v[4], u[4];
#pragma unroll
        for (int k = 0; k < 4; k++) { v[k] = zr[lane + 32 * k]; u[k] = zar[lane + 32 * k]; }
        float sz = 0.0f, sa = 0.0f, dd = 0.0f;
#pragma unroll
        for (int k = 0; k < 4; k++) {
            sz += v[k].x * v[k].x + v[k].y * v[k].y + v[k].z * v[k].z + v[k].w * v[k].w;
            sa += u[k].x * u[k].x + u[k].y * u[k].y + u[k].z * u[k].z + u[k].w * u[k].w;
            dd += v[k].x * u[k].x + v[k].y * u[k].y + v[k].z * u[k].z + v[k].w * u[k].w;
        }
#pragma unroll
        for (int o = 16; o; o >>= 1) {
            sz += __shfl_xor_sync(0xffffffffu, sz, o);
            sa += __shfl_xor_sync(0xffffffffu, sa, o);
            dd += __shfl_xor_sync(0xffffffffu, dd, o);
        }
        float invz  = 1.0f / fmaxf(sqrtf(sz), c_eps);
        float invza = 1.0f / fmaxf(sqrtf(sa), c_eps);
#pragma unroll
        for (int k = 0; k < 4; k++) {
            __half2 h0 = __floats2half2_rn(v[k].x * invz, v[k].y * invz);
            __half2 h1 = __floats2half2_rn(v[k].z * invz, v[k].w * invz);
            uint2 packed = make_uint2(*reinterpret_cast<unsigned*>(&h0),
                                      *reinterpret_cast<unsigned*>(&h1));
            reinterpret_cast<uint2*>(g_zh + (size_t)row * D)[lane + 32 * k] = packed;
        }
        if (lane == 0) g_eadv[row] = expf(dd * invz * invza * c_invT);
    }

    // ================= Phase A': label sort (block 0 only) =================
    if (blockIdx.x == 0) {
        if (t == 0) { ok = 1; g_done = 0u; }
        __syncthreads();
        // int64 labels in [0,100): odd 32-bit words are 0, even in range.
        bool good = true;
        for (int k = t; k < N / 2; k += THREADS) {
            int lo = lab[2 * k];
            int hi = lab[2 * k + 1];
            if (hi != 0 || lo < 0 || lo >= NCLASS) good = false;
        }
        if (!good) atomicExch(&ok, 0);
        __syncthreads();
        int is64 = ok;

        for (int i = t; i < N; i += THREADS) g_sl[i] = is64 ? lab[2 * i] : lab[i];
        for (int c = lane; c < NCLASS; c += 32) whist[w][c] = 0;
        __syncthreads();

        // count pass: warp w owns rows [w*512, w*512+512), 16 iters of 32
        int rbase = w * 512;
#pragma unroll 1
        for (int it = 0; it < 16; it++) {
            int c = g_sl[rbase + it * 32 + lane];
            unsigned mask = __match_any_sync(0xffffffffu, c);
            int leader = __ffs(mask) - 1;
            if (lane == leader) whist[w][c] += __popc(mask);
            __syncwarp();
        }
        __syncthreads();

        // cross-warp exclusive scan per class (thread per class, 8 steps)
        if (t < NCLASS) {
            int run = 0;
#pragma unroll
            for (int k = 0; k < 8; k++) {
                int v = whist[k][t];
                whist[k][t] = run;
                run += v;
            }
            cls_cnt[t] = run;
        }
        __syncthreads();

        // class offsets: warp 0, 4 SHFL scan segments over 100 counts
        if (w == 0) {
            int carry = 0;
#pragma unroll
            for (int seg = 0; seg < 4; seg++) {
                int c = seg * 32 + lane;
                int v = (c < NCLASS) ? cls_cnt[c] : 0;
                int inc = v;
#pragma unroll
                for (int o = 1; o < 32; o <<= 1) {
                    int y = __shfl_up_sync(0xffffffffu, inc, o);
                    if (lane >= o) inc += y;
                }
                if (c < NCLASS) cls_off[c] = inc - v + carry;
                carry += __shfl_sync(0xffffffffu, inc, 31);
            }
        }
        __syncthreads();

        // stable emit
#pragma unroll 1
        for (int it = 0; it < 16; it++) {
            int row = rbase + it * 32 + lane;
            int c = g_sl[row];
            unsigned mask = __match_any_sync(0xffffffffu, c);
            int rank = __popc(mask & ((1u << lane) - 1u));
            int base = whist[w][c];
            int pos = cls_off[c] + base + rank;
            g_members[pos] = row;
            g_sclass[pos] = c;
            int leader = __ffs(mask) - 1;
            if (lane == leader) whist[w][c] = base + __popc(mask);
            __syncwarp();
        }
        if (t < NCLASS) { g_count[t] = cls_cnt[t]; g_offset[t] = cls_off[t]; }
    }

    // ================= grid barrier =================
    grid_sync();

    // ================= Phase B: intra (warp per slot) =================
    {
        int s = blockIdx.x * 8 + w;        // slot 0..4095
        int i = g_members[s];
        int c = g_sclass[s];
        int off = g_offset[c];
        int cnt = g_count[c];

        // row i lane-share as 8 half2 registers
        __half2 a[8];
        {
            const uint4* rp = reinterpret_cast<const uint4*>(g_zh + (size_t)i * D);
            uint4 u0 = rp[lane], u1 = rp[lane + 32];
            const __half2* H0 = reinterpret_cast<const __half2*>(&u0);
            const __half2* H1 = reinterpret_cast<const __half2*>(&u1);
#pragma unroll
            for (int k = 0; k < 4; k++) { a[k] = H0[k]; a[4 + k] = H1[k]; }
        }

        float acc = 0.0f;
        int m = 0;
        for (; m + 4 <= cnt; m += 4) {
            int j0 = g_members[off + m];
            int j1 = g_members[off + m + 1];
            int j2 = g_members[off + m + 2];
            int j3 = g_members[off + m + 3];
            const uint4* A0 = reinterpret_cast<const uint4*>(g_zh + (size_t)j0 * D);
            const uint4* A1 = reinterpret_cast<const uint4*>(g_zh + (size_t)j1 * D);
            const uint4* A2 = reinterpret_cast<const uint4*>(g_zh + (size_t)j2 * D);
            const uint4* A3 = reinterpret_cast<const uint4*>(g_zh + (size_t)j3 * D);
            uint4 u0a = A0[lane], u0b = A0[lane + 32];
            uint4 u1a = A1[lane], u1b = A1[lane + 32];
            uint4 u2a = A2[lane], u2b = A2[lane + 32];
            uint4 u3a = A3[lane], u3b = A3[lane + 32];
            float s0 = dot_h2(a, u0a, u0b);
            float s1 = dot_h2(a, u1a, u1b);
            float s2 = dot_h2(a, u2a, u2b);
            float s3 = dot_h2(a, u3a, u3b);
#pragma unroll
            for (int o = 16; o; o >>= 1) {
                s0 += __shfl_xor_sync(0xffffffffu, s0, o);
                s1 += __shfl_xor_sync(0xffffffffu, s1, o);
                s2 += __shfl_xor_sync(0xffffffffu, s2, o);
                s3 += __shfl_xor_sync(0xffffffffu, s3, o);
            }
            float e0 = __expf(s0 * c_invT);
            float e1 = __expf(s1 * c_invT);
            float e2 = __expf(s2 * c_invT);
            float e3 = __expf(s3 * c_invT);
            acc += (j0 != i) ? e0 : 0.0f;
            acc += (j1 != i) ? e1 : 0.0f;
            acc += (j2 != i) ? e2 : 0.0f;
            acc += (j3 != i) ? e3 : 0.0f;
        }
        for (; m < cnt; m++) {
            int j0 = g_members[off + m];
            const uint4* A0 = reinterpret_cast<const uint4*>(g_zh + (size_t)j0 * D);
            uint4 u0a = A0[lane], u0b = A0[lane + 32];
            float s0 = dot_h2(a, u0a, u0b);
#pragma unroll
            for (int o = 16; o; o >>= 1) s0 += __shfl_xor_sync(0xffffffffu, s0, o);
            acc += (j0 != i) ? __expf(s0 * c_invT) : 0.0f;
        }

        if (lane == 0) warp_loss[w] = log1pf(acc / g_eadv[i]);
    }
    __syncthreads();

    // ================= Phase C: ticketed final reduction =================
    if (t == 0) {
        float bsum = 0.0f;
#pragma unroll
        for (int ww = 0; ww < 8; ww++) bsum += warp_loss[ww];
        g_partial[blockIdx.x] = bsum;
        __threadfence();
        unsigned int ticket = atomicAdd(&g_done, 1u);
        is_last = (ticket == GRID - 1);
    }
    __syncthreads();

    if (is_last) {
        __threadfence();
        smr[t] = g_partial[t] + g_partial[t + THREADS];
        __syncthreads();
#pragma unroll
        for (int o = THREADS / 2; o > 0; o >>= 1) {
            if (t < o) smr[t] += smr[t + o];
            __syncthreads();
        }
        if (t == 0) out[0] = smr[0] * (1.0f / (float)N);
    }
}

extern "C" void kernel_launch(void* const* d_in, const int* in_sizes, int n_in,
                              void* d_out, int out_size) {
    const float* z   = (const float*)d_in[0];
    const float* za  = (const float*)d_in[1];
    const int*   lab = (const int*)d_in[2];
    float* out = (float*)d_out;

    k_all<<<GRID, THREADS>>>(z, za, lab, out);
}